// round 6
// baseline (speedup 1.0000x reference)
#include <cuda_runtime.h>
#include <cuda_bf16.h>

// Problem: TriggerGenerator_66889820668158
// Output: concat(trig [2048,256], edge_probs [2096128,1]) = 2620416 f32

#define N_NODES   2048
#define FDIM      256
#define HID       64
#define TEMPLATE  10
#define TRIG_ELEMS (N_NODES * FDIM)

__device__ float g_s[FDIM];
__device__ float g_pa[N_NODES * HID];   // pa + eb1 folded
__device__ float g_pb[N_NODES * HID];

// ---- packed f32x2 helpers (Blackwell FFMA2/FADD2 path) ----------------------
typedef unsigned long long u64;

__device__ __forceinline__ u64 add_f32x2(u64 a, u64 b) {
    u64 r; asm("add.rn.f32x2 %0, %1, %2;" : "=l"(r) : "l"(a), "l"(b)); return r;
}
__device__ __forceinline__ u64 fma_f32x2(u64 a, u64 b, u64 c) {
    u64 r; asm("fma.rn.f32x2 %0, %1, %2, %3;" : "=l"(r) : "l"(a), "l"(b), "l"(c)); return r;
}
__device__ __forceinline__ float lo_f(u64 v) { return __uint_as_float((unsigned)v); }
__device__ __forceinline__ float hi_f(u64 v) { return __uint_as_float((unsigned)(v >> 32)); }
__device__ __forceinline__ u64 pack_f(float lo, float hi) {
    return ((u64)__float_as_uint(hi) << 32) | (u64)__float_as_uint(lo);
}

// ---------------------------------------------------------------------------
// K1: GCN collapsed to one vector chain (template rows identical; A=ones/T
// is identity on identical rows). Parallelized: 1024 threads, split-K per
// layer with shfl_xor reductions; w1/w2 register-prefetched to overlap the
// cold-DRAM latency with the proto gather. (R3 showed K1 = 29.5us latency
// bound at block=256 / 1-thread-per-output.)
// ---------------------------------------------------------------------------
__global__ void __launch_bounds__(1024)
k1_gcn(const float* __restrict__ clean,
       const int*   __restrict__ sel,
       const float* __restrict__ w1, const float* __restrict__ b1,
       const float* __restrict__ w2, const float* __restrict__ b2,
       const float* __restrict__ w3, const float* __restrict__ b3)
{
    __shared__ float proto[FDIM];
    __shared__ float h1[HID];
    __shared__ float h2[HID];
    int t = threadIdx.x;              // 0..1023

    // ---- prefetch w1 (16 regs) and w2 (4 regs) before anything stalls ----
    int out16 = t >> 4;               // 0..63  (layer1/2 output index)
    int sub16 = t & 15;               // 0..15  (split-K slice)
    float w1r[16];
    #pragma unroll
    for (int q = 0; q < 16; q++)
        w1r[q] = w1[(sub16 + 16 * q) * HID + out16];
    float w2r[4];
    #pragma unroll
    for (int q = 0; q < 4; q++)
        w2r[q] = w2[(sub16 + 16 * q) * HID + out16];

    // ---- proto = mean of 10 selected rows (256 threads, overlaps prefetch) --
    if (t < FDIM) {
        float acc = 0.f;
        #pragma unroll
        for (int n = 0; n < TEMPLATE; n++)
            acc += clean[(long long)sel[n] * FDIM + t];
        proto[t] = acc * (1.0f / TEMPLATE);
    }
    __syncthreads();

    // ---- layer 1: h1 = relu(W1^T proto + b1), 16-way split-K ----
    {
        float p = 0.f;
        #pragma unroll
        for (int q = 0; q < 16; q++)
            p = fmaf(proto[sub16 + 16 * q], w1r[q], p);
        #pragma unroll
        for (int m = 8; m >= 1; m >>= 1)
            p += __shfl_xor_sync(0xffffffffu, p, m);
        if (sub16 == 0) h1[out16] = fmaxf(p + b1[out16], 0.f);
    }
    __syncthreads();

    // ---- layer 2: h2 = relu(W2^T h1 + b2), 16-way split-K ----
    {
        float p = 0.f;
        #pragma unroll
        for (int q = 0; q < 4; q++)
            p = fmaf(h1[sub16 + 16 * q], w2r[q], p);
        #pragma unroll
        for (int m = 8; m >= 1; m >>= 1)
            p += __shfl_xor_sync(0xffffffffu, p, m);
        if (sub16 == 0) h2[out16] = fmaxf(p + b2[out16], 0.f);
    }
    __syncthreads();

    // ---- layer 3: s = sigmoid(W3^T h2 + b3), 4-way split-K (256 outputs) ----
    {
        int out4 = t >> 2;            // 0..255
        int sub4 = t & 3;             // 0..3
        float p = 0.f;
        #pragma unroll
        for (int q = 0; q < 16; q++) {
            int f = sub4 + 4 * q;
            p = fmaf(h2[f], w3[f * FDIM + out4], p);
        }
        p += __shfl_xor_sync(0xffffffffu, p, 2);
        p += __shfl_xor_sync(0xffffffffu, p, 1);
        if (sub4 == 0) g_s[out4] = 1.0f / (1.0f + __expf(-(p + b3[out4])));
    }
}

// ---------------------------------------------------------------------------
// K2: build trig rows (write to out), and pa/pb = trig @ ew1 halves.
// 128 blocks x 256 threads; each block owns 16 rows.
// ---------------------------------------------------------------------------
__global__ void __launch_bounds__(256)
k2_trig_pab(const float* __restrict__ noise,
            const float* __restrict__ ew1,
            const float* __restrict__ eb1,
            float* __restrict__ out_trig)
{
    __shared__ float s_s[FDIM];
    __shared__ float t_s[16][FDIM];
    int tid = threadIdx.x;            // 256
    s_s[tid] = g_s[tid];
    __syncthreads();

    int base = blockIdx.x * 16;
    #pragma unroll
    for (int r = 0; r < 16; r++) {
        int i = base + r;
        float tv = s_s[tid];
        if (i >= TEMPLATE) tv += 0.1f * noise[(i - TEMPLATE) * FDIM + tid];
        t_s[r][tid] = tv;
        out_trig[i * FDIM + tid] = tv;
    }
    __syncthreads();

    int kk  = tid & 127;
    int rg  = tid >> 7;               // 0/1 -> rows [0..7] / [8..15]
    int col = kk & 63;
    int foff = (kk < HID) ? 0 : FDIM; // pa uses ew1[0:256], pb uses ew1[256:512]

    float acc[8];
    #pragma unroll
    for (int r = 0; r < 8; r++) acc[r] = 0.f;

    #pragma unroll 4
    for (int f = 0; f < FDIM; f += 4) {
        float w0 = ew1[(foff + f    ) * HID + col];
        float w1 = ew1[(foff + f + 1) * HID + col];
        float w2 = ew1[(foff + f + 2) * HID + col];
        float w3 = ew1[(foff + f + 3) * HID + col];
        #pragma unroll
        for (int r = 0; r < 8; r++) {
            float4 t4 = *(const float4*)&t_s[rg * 8 + r][f];
            acc[r] = fmaf(t4.x, w0, acc[r]);
            acc[r] = fmaf(t4.y, w1, acc[r]);
            acc[r] = fmaf(t4.z, w2, acc[r]);
            acc[r] = fmaf(t4.w, w3, acc[r]);
        }
    }

    #pragma unroll
    for (int r = 0; r < 8; r++) {
        int i = base + rg * 8 + r;
        if (kk < HID) g_pa[i * HID + kk]        = acc[r] + eb1[kk];
        else          g_pb[i * HID + (kk - 64)] = acc[r];
    }
}

// ---------------------------------------------------------------------------
// K3: upper-triangle pairs, 64x64 tiles, 4x4 micro-tile, f32x2-packed k-dim.
// TSTRIDE=66 keeps LDS.64 aligned and banks conflict-free.
// ---------------------------------------------------------------------------
#define TS 64
#define TSTRIDE 66

__global__ void __launch_bounds__(256)
k3_edges(const float* __restrict__ ew2,
         const float* __restrict__ eb2,
         float* __restrict__ out_edge)
{
    int tjb = blockIdx.x;
    int tib = blockIdx.y;
    if (tib > tjb) return;

    __shared__ __align__(8) float pa_s[TS * TSTRIDE];
    __shared__ __align__(8) float pb_s[TS * TSTRIDE];
    __shared__ __align__(8) float w_s[HID];

    int tid = threadIdx.x;  // 256
    int base_i = tib * TS;
    int base_j = tjb * TS;

    for (int idx = tid; idx < TS * HID; idx += 256) {
        int row = idx >> 6, k = idx & 63;
        pa_s[row * TSTRIDE + k] = g_pa[(base_i + row) * HID + k];
        pb_s[row * TSTRIDE + k] = g_pb[(base_j + row) * HID + k];
    }
    if (tid < HID) w_s[tid] = ew2[tid];
    __syncthreads();

    int r = tid >> 4;   // 0..15
    int c = tid & 15;   // 0..15

    u64 acc2[4][4];
    #pragma unroll
    for (int a = 0; a < 4; a++)
        #pragma unroll
        for (int b = 0; b < 4; b++) acc2[a][b] = 0ull;

    #pragma unroll 4
    for (int k = 0; k < HID; k += 2) {
        u64 w2 = *(const u64*)&w_s[k];
        u64 av2[4], bv2[4];
        #pragma unroll
        for (int a = 0; a < 4; a++)
            av2[a] = *(const u64*)&pa_s[(r + 16 * a) * TSTRIDE + k];
        #pragma unroll
        for (int b = 0; b < 4; b++)
            bv2[b] = *(const u64*)&pb_s[(c + 16 * b) * TSTRIDE + k];

        #pragma unroll
        for (int a = 0; a < 4; a++)
            #pragma unroll
            for (int b = 0; b < 4; b++) {
                u64 s = add_f32x2(av2[a], bv2[b]);
                float h0 = fmaxf(lo_f(s), 0.f);
                float h1 = fmaxf(hi_f(s), 0.f);
                acc2[a][b] = fma_f32x2(pack_f(h0, h1), w2, acc2[a][b]);
            }
    }

    float bias = eb2[0];
    #pragma unroll
    for (int a = 0; a < 4; a++) {
        int i = base_i + r + 16 * a;
        int ebase = i * (N_NODES - 1) - (i * (i - 1)) / 2 - i - 1;
        #pragma unroll
        for (int b = 0; b < 4; b++) {
            int j = base_j + c + 16 * b;
            if (i < j) {
                float x = lo_f(acc2[a][b]) + hi_f(acc2[a][b]) + bias;
                out_edge[ebase + j] = 1.0f / (1.0f + __expf(-x));
            }
        }
    }
}

// ---------------------------------------------------------------------------
extern "C" void kernel_launch(void* const* d_in, const int* in_sizes, int n_in,
                              void* d_out, int out_size)
{
    const float* clean  = (const float*)d_in[0];
    const int*   sel    = (const int*)  d_in[1];
    const float* noise  = (const float*)d_in[2];
    const float* g1w    = (const float*)d_in[3];
    const float* g1b    = (const float*)d_in[4];
    const float* g2w    = (const float*)d_in[5];
    const float* g2b    = (const float*)d_in[6];
    const float* g3w    = (const float*)d_in[7];
    const float* g3b    = (const float*)d_in[8];
    const float* ew1    = (const float*)d_in[9];
    const float* eb1    = (const float*)d_in[10];
    const float* ew2    = (const float*)d_in[11];
    const float* eb2    = (const float*)d_in[12];

    float* out      = (float*)d_out;
    float* out_edge = out + TRIG_ELEMS;

    k1_gcn<<<1, 1024>>>(clean, sel, g1w, g1b, g2w, g2b, g3w, g3b);
    k2_trig_pab<<<128, 256>>>(noise, ew1, eb1, out);
    k3_edges<<<dim3(32, 32), 256>>>(ew2, eb2, out_edge);
}

// round 8
// speedup vs baseline: 1.0406x; 1.0406x over previous
#include <cuda_runtime.h>
#include <cuda_bf16.h>

// Problem: TriggerGenerator_66889820668158
// Output: concat(trig [2048,256], edge_probs [2096128,1]) = 2620416 f32

#define N_NODES   2048
#define FDIM      256
#define HID       64
#define TEMPLATE  10
#define TRIG_ELEMS (N_NODES * FDIM)

__device__ float g_s[FDIM];
__device__ float g_pa[N_NODES * HID];   // pa + eb1 folded
__device__ float g_pb[N_NODES * HID];

typedef unsigned long long u64;

__device__ __forceinline__ float lo_f(u64 v) { return __uint_as_float((unsigned)v); }
__device__ __forceinline__ float hi_f(u64 v) { return __uint_as_float((unsigned)(v >> 32)); }

// One edge-cell k-pair update, fully inside asm so the pair halves coalesce
// into register pairs (no integer 64-bit shift/or chains in SASS):
//   s = a + b (f32x2); lo/hi = relu halves; acc += s * w (f32x2)
// 4 real instructions per 2 k's: FADD2, 2x FMNMX, FFMA2.
__device__ __forceinline__ void cell_update(u64 av, u64 bv, u64 w, u64 &acc) {
    asm("{\n\t"
        ".reg .f32 lo, hi;\n\t"
        ".reg .b64 s;\n\t"
        "add.rn.f32x2 s, %1, %2;\n\t"
        "mov.b64 {lo, hi}, s;\n\t"
        "max.f32 lo, lo, 0f00000000;\n\t"
        "max.f32 hi, hi, 0f00000000;\n\t"
        "mov.b64 s, {lo, hi};\n\t"
        "fma.rn.f32x2 %0, s, %3, %0;\n\t"
        "}\n"
        : "+l"(acc) : "l"(av), "l"(bv), "l"(w));
}

// ---------------------------------------------------------------------------
// K1: GCN collapsed to one vector chain (template rows identical; A=ones/T
// is identity on identical rows). 1024 threads, split-K + shfl reductions,
// w1/w2 register-prefetched. (Steady-state cost small; cold-cache ncu 16us.)
// ---------------------------------------------------------------------------
__global__ void __launch_bounds__(1024)
k1_gcn(const float* __restrict__ clean,
       const int*   __restrict__ sel,
       const float* __restrict__ w1, const float* __restrict__ b1,
       const float* __restrict__ w2, const float* __restrict__ b2,
       const float* __restrict__ w3, const float* __restrict__ b3)
{
    __shared__ float proto[FDIM];
    __shared__ float h1[HID];
    __shared__ float h2[HID];
    int t = threadIdx.x;              // 0..1023

    int out16 = t >> 4;               // 0..63
    int sub16 = t & 15;               // 0..15
    float w1r[16];
    #pragma unroll
    for (int q = 0; q < 16; q++)
        w1r[q] = w1[(sub16 + 16 * q) * HID + out16];
    float w2r[4];
    #pragma unroll
    for (int q = 0; q < 4; q++)
        w2r[q] = w2[(sub16 + 16 * q) * HID + out16];

    if (t < FDIM) {
        float acc = 0.f;
        #pragma unroll
        for (int n = 0; n < TEMPLATE; n++)
            acc += clean[(long long)sel[n] * FDIM + t];
        proto[t] = acc * (1.0f / TEMPLATE);
    }
    __syncthreads();

    {
        float p = 0.f;
        #pragma unroll
        for (int q = 0; q < 16; q++)
            p = fmaf(proto[sub16 + 16 * q], w1r[q], p);
        #pragma unroll
        for (int m = 8; m >= 1; m >>= 1)
            p += __shfl_xor_sync(0xffffffffu, p, m);
        if (sub16 == 0) h1[out16] = fmaxf(p + b1[out16], 0.f);
    }
    __syncthreads();

    {
        float p = 0.f;
        #pragma unroll
        for (int q = 0; q < 4; q++)
            p = fmaf(h1[sub16 + 16 * q], w2r[q], p);
        #pragma unroll
        for (int m = 8; m >= 1; m >>= 1)
            p += __shfl_xor_sync(0xffffffffu, p, m);
        if (sub16 == 0) h2[out16] = fmaxf(p + b2[out16], 0.f);
    }
    __syncthreads();

    {
        int out4 = t >> 2;            // 0..255
        int sub4 = t & 3;             // 0..3
        float p = 0.f;
        #pragma unroll
        for (int q = 0; q < 16; q++) {
            int f = sub4 + 4 * q;
            p = fmaf(h2[f], w3[f * FDIM + out4], p);
        }
        p += __shfl_xor_sync(0xffffffffu, p, 2);
        p += __shfl_xor_sync(0xffffffffu, p, 1);
        if (sub4 == 0) g_s[out4] = 1.0f / (1.0f + __expf(-(p + b3[out4])));
    }
}

// ---------------------------------------------------------------------------
// K2: build trig rows (write to out), and pa/pb = trig @ ew1 halves.
// 128 blocks x 256 threads; each block owns 16 rows.
// ---------------------------------------------------------------------------
__global__ void __launch_bounds__(256)
k2_trig_pab(const float* __restrict__ noise,
            const float* __restrict__ ew1,
            const float* __restrict__ eb1,
            float* __restrict__ out_trig)
{
    __shared__ float s_s[FDIM];
    __shared__ float t_s[16][FDIM];
    int tid = threadIdx.x;            // 256
    s_s[tid] = g_s[tid];
    __syncthreads();

    int base = blockIdx.x * 16;
    #pragma unroll
    for (int r = 0; r < 16; r++) {
        int i = base + r;
        float tv = s_s[tid];
        if (i >= TEMPLATE) tv += 0.1f * noise[(i - TEMPLATE) * FDIM + tid];
        t_s[r][tid] = tv;
        out_trig[i * FDIM + tid] = tv;
    }
    __syncthreads();

    int kk  = tid & 127;
    int rg  = tid >> 7;               // 0/1 -> rows [0..7] / [8..15]
    int col = kk & 63;
    int foff = (kk < HID) ? 0 : FDIM; // pa uses ew1[0:256], pb uses ew1[256:512]

    float acc[8];
    #pragma unroll
    for (int r = 0; r < 8; r++) acc[r] = 0.f;

    #pragma unroll 4
    for (int f = 0; f < FDIM; f += 4) {
        float w0 = ew1[(foff + f    ) * HID + col];
        float w1 = ew1[(foff + f + 1) * HID + col];
        float w2 = ew1[(foff + f + 2) * HID + col];
        float w3 = ew1[(foff + f + 3) * HID + col];
        #pragma unroll
        for (int r = 0; r < 8; r++) {
            float4 t4 = *(const float4*)&t_s[rg * 8 + r][f];
            acc[r] = fmaf(t4.x, w0, acc[r]);
            acc[r] = fmaf(t4.y, w1, acc[r]);
            acc[r] = fmaf(t4.z, w2, acc[r]);
            acc[r] = fmaf(t4.w, w3, acc[r]);
        }
    }

    #pragma unroll
    for (int r = 0; r < 8; r++) {
        int i = base + rg * 8 + r;
        if (kk < HID) g_pa[i * HID + kk]        = acc[r] + eb1[kk];
        else          g_pb[i * HID + (kk - 64)] = acc[r];
    }
}

// ---------------------------------------------------------------------------
// K3: upper-triangle pairs. 1D triangular grid (528 live blocks, no dead
// launches). 64x64 tile, 4x4 micro-tile, k-dim in f32x2 pairs via clean
// single-asm cell (FADD2 + 2xFMNMX + FFMA2; no int64 pack chains).
// TSTRIDE=66: LDS.64 aligned; bv banks (2c..) conflict-free.
// ---------------------------------------------------------------------------
#define TS 64
#define TSTRIDE 66
#define NTILES 32
#define NPAIRS (NTILES * (NTILES + 1) / 2)   // 528

__global__ void __launch_bounds__(256)
k3_edges(const float* __restrict__ ew2,
         const float* __restrict__ eb2,
         float* __restrict__ out_edge)
{
    // decode linear pair index p -> (tib <= tjb)
    int p = blockIdx.x;
    int tjb = (int)((sqrtf(8.0f * (float)p + 1.0f) - 1.0f) * 0.5f);
    while ((tjb + 1) * (tjb + 2) / 2 <= p) tjb++;
    while (tjb * (tjb + 1) / 2 > p) tjb--;
    int tib = p - tjb * (tjb + 1) / 2;   // 0..tjb

    __shared__ __align__(8) float pa_s[TS * TSTRIDE];
    __shared__ __align__(8) float pb_s[TS * TSTRIDE];
    __shared__ __align__(8) float w_s[HID];

    int tid = threadIdx.x;  // 256
    int base_i = tib * TS;
    int base_j = tjb * TS;

    // fill with float2 (8B) loads/stores: 2048 pairs per array, 256 threads
    for (int idx = tid; idx < TS * HID / 2; idx += 256) {
        int row = idx >> 5;            // /32 pairs per row
        int k2i = (idx & 31) * 2;
        float2 va = *(const float2*)&g_pa[(base_i + row) * HID + k2i];
        float2 vb = *(const float2*)&g_pb[(base_j + row) * HID + k2i];
        *(float2*)&pa_s[row * TSTRIDE + k2i] = va;
        *(float2*)&pb_s[row * TSTRIDE + k2i] = vb;
    }
    if (tid < HID) w_s[tid] = ew2[tid];
    __syncthreads();

    int r = tid >> 4;   // 0..15
    int c = tid & 15;   // 0..15

    u64 acc2[4][4];
    #pragma unroll
    for (int a = 0; a < 4; a++)
        #pragma unroll
        for (int b = 0; b < 4; b++) acc2[a][b] = 0ull;

    #pragma unroll 4
    for (int k = 0; k < HID; k += 2) {
        u64 w2 = *(const u64*)&w_s[k];
        u64 av2[4], bv2[4];
        #pragma unroll
        for (int a = 0; a < 4; a++)
            av2[a] = *(const u64*)&pa_s[(r + 16 * a) * TSTRIDE + k];
        #pragma unroll
        for (int b = 0; b < 4; b++)
            bv2[b] = *(const u64*)&pb_s[(c + 16 * b) * TSTRIDE + k];

        #pragma unroll
        for (int a = 0; a < 4; a++)
            #pragma unroll
            for (int b = 0; b < 4; b++)
                cell_update(av2[a], bv2[b], w2, acc2[a][b]);
    }

    float bias = eb2[0];
    #pragma unroll
    for (int a = 0; a < 4; a++) {
        int i = base_i + r + 16 * a;
        int ebase = i * (N_NODES - 1) - (i * (i - 1)) / 2 - i - 1;
        #pragma unroll
        for (int b = 0; b < 4; b++) {
            int j = base_j + c + 16 * b;
            if (i < j) {
                float x = lo_f(acc2[a][b]) + hi_f(acc2[a][b]) + bias;
                out_edge[ebase + j] = 1.0f / (1.0f + __expf(-x));
            }
        }
    }
}

// ---------------------------------------------------------------------------
extern "C" void kernel_launch(void* const* d_in, const int* in_sizes, int n_in,
                              void* d_out, int out_size)
{
    const float* clean  = (const float*)d_in[0];
    const int*   sel    = (const int*)  d_in[1];
    const float* noise  = (const float*)d_in[2];
    const float* g1w    = (const float*)d_in[3];
    const float* g1b    = (const float*)d_in[4];
    const float* g2w    = (const float*)d_in[5];
    const float* g2b    = (const float*)d_in[6];
    const float* g3w    = (const float*)d_in[7];
    const float* g3b    = (const float*)d_in[8];
    const float* ew1    = (const float*)d_in[9];
    const float* eb1    = (const float*)d_in[10];
    const float* ew2    = (const float*)d_in[11];
    const float* eb2    = (const float*)d_in[12];

    float* out      = (float*)d_out;
    float* out_edge = out + TRIG_ELEMS;

    k1_gcn<<<1, 1024>>>(clean, sel, g1w, g1b, g2w, g2b, g3w, g3b);
    k2_trig_pab<<<128, 256>>>(noise, ew1, eb1, out);
    k3_edges<<<NPAIRS, 256>>>(ew2, eb2, out_edge);
}